// round 2
// baseline (speedup 1.0000x reference)
#include <cuda_runtime.h>
#include <cuda_bf16.h>
#include <cstdint>

#define NN 10000
#define EE 160000
#define HH 256
#define GG 64
#define BM 64
#define NODE_BLKS 6
#define EDGE_BLKS 92
#define HEAD_SPAN (NODE_BLKS + EDGE_BLKS)
#define GRID1 (3 * HEAD_SPAN)

// smem layout (floats)
#define SM_BUFA 0
#define SM_BUFB 16384
#define SM_W    32768
#define SM_ACC  40960
#define SM_ROWG 57344
#define SMEM_BYTES ((57344 + 64) * 4)   // 229,632 B

__device__ float g_pooled[3 * GG * 2 * HH];   // [head][g][512]

// ---- packed f32x2 helpers ----
__device__ __forceinline__ unsigned long long pack2s(float v) {
    unsigned long long r; unsigned int i = __float_as_uint(v);
    asm("mov.b64 %0, {%1, %2};" : "=l"(r) : "r"(i), "r"(i));
    return r;
}
__device__ __forceinline__ unsigned long long pack2f(float a, float b) {
    unsigned long long r;
    unsigned int ia = __float_as_uint(a), ib = __float_as_uint(b);
    asm("mov.b64 %0, {%1, %2};" : "=l"(r) : "r"(ia), "r"(ib));
    return r;
}
__device__ __forceinline__ void fma2(unsigned long long &d,
                                     unsigned long long a, unsigned long long b) {
    asm("fma.rn.f32x2 %0, %1, %2, %0;" : "+l"(d) : "l"(a), "l"(b));
}
__device__ __forceinline__ float2 unpack2(unsigned long long v) {
    unsigned int lo, hi;
    asm("mov.b64 {%0, %1}, %2;" : "=r"(lo), "=r"(hi) : "l"(v));
    return make_float2(__uint_as_float(lo), __uint_as_float(hi));
}
__device__ __forceinline__ float silu(float x) {
    return __fdividef(x, 1.0f + __expf(-x));
}

// ---- zero scratch + output ----
__global__ void zero_kernel(float* out, int out_size) {
    int i = blockIdx.x * 256 + threadIdx.x;
    int np = 3 * GG * 2 * HH;
    if (i < np) g_pooled[i] = 0.0f;
    else if (i - np < out_size) out[i - np] = 0.0f;
}

// ---- fused 3-layer MLP1 + graph pooling, all heads & branches ----
__global__ void __launch_bounds__(256, 1)
fused_mlp1_pool(const float* __restrict__ nf0, const float* __restrict__ ef0,
                const int* __restrict__ ei0, const int* __restrict__ bt0,
                const float* __restrict__ nf1, const float* __restrict__ ef1,
                const int* __restrict__ ei1, const int* __restrict__ bt1,
                const float* __restrict__ nf2, const float* __restrict__ ef2,
                const int* __restrict__ ei2, const int* __restrict__ bt2,
                const float* __restrict__ W1, const float* __restrict__ b1,
                const float* __restrict__ W2, const float* __restrict__ b2,
                const float* __restrict__ W3, const float* __restrict__ b3) {
    extern __shared__ float sm[];
    float* bufA = sm + SM_BUFA;
    float* bufB = sm + SM_BUFB;
    float* wt   = sm + SM_W;
    float* accs = sm + SM_ACC;
    int*   rowg = (int*)(sm + SM_ROWG);

    const int tid = threadIdx.x;
    const int head = blockIdx.x / HEAD_SPAN;
    const int j    = blockIdx.x % HEAD_SPAN;

    const float* nf = (head == 0) ? nf0 : (head == 1) ? nf1 : nf2;
    const float* ef = (head == 0) ? ef0 : (head == 1) ? ef1 : ef2;
    const int*   ei = (head == 0) ? ei0 : (head == 1) ? ei1 : ei2;
    const int*   bt = (head == 0) ? bt0 : (head == 1) ? bt1 : bt2;

    int branch, P, p, nrows;
    if (j < NODE_BLKS) { branch = 0; P = NODE_BLKS; p = j;             nrows = NN; }
    else               { branch = 1; P = EDGE_BLKS; p = j - NODE_BLKS; nrows = EE; }
    const float* feats = branch ? ef : nf;
    const int ntiles = (nrows + BM - 1) >> 6;

    for (int i = tid; i < GG * HH; i += 256) accs[i] = 0.0f;

    const float* Ws[3] = {W1, W2, W3};
    const float* Bs[3] = {b1, b2, b3};
    const int tr = tid >> 5;   // warp id = row group
    const int tc = tid & 31;   // col group (8 cols each)

    for (int t = p; t < ntiles; t += P) {
        const int row0 = t << 6;
        const int rem  = nrows - row0;

        if (tid < BM) {
            int r = row0 + tid;
            int g = -1;
            if (r < nrows) g = branch ? bt[ei[EE + r]] : bt[r];
            rowg[tid] = g;
        }
        // load input tile (zero-pad tail rows)
        {
            const float4* f4 = (const float4*)feats + (size_t)row0 * (HH / 4);
            const float4 z = make_float4(0.f, 0.f, 0.f, 0.f);
            #pragma unroll
            for (int i = 0; i < 16; ++i) {
                int idx = tid + i * 256;
                ((float4*)bufA)[idx] = ((idx >> 6) < rem) ? f4[idx] : z;
            }
        }
        __syncthreads();

        float* IN  = bufA;
        float* OUT = bufB;

        #pragma unroll
        for (int l = 0; l < 3; ++l) {
            const float* W  = Ws[l];
            const float* Bv = Bs[l];

            float4 bv0 = *(const float4*)(Bv + tc * 8);
            float4 bv1 = *(const float4*)(Bv + tc * 8 + 4);
            unsigned long long acc[8][4];
            #pragma unroll
            for (int ri = 0; ri < 8; ++ri) {
                acc[ri][0] = pack2f(bv0.x, bv0.y);
                acc[ri][1] = pack2f(bv0.z, bv0.w);
                acc[ri][2] = pack2f(bv1.x, bv1.y);
                acc[ri][3] = pack2f(bv1.z, bv1.w);
            }

            for (int kb = 0; kb < 8; ++kb) {
                // stage 32x256 W tile
                const float4* wsrc = (const float4*)(W + kb * 32 * HH);
                #pragma unroll
                for (int i = 0; i < 8; ++i)
                    ((float4*)wt)[tid + i * 256] = wsrc[tid + i * 256];
                __syncthreads();

                #pragma unroll
                for (int k4 = 0; k4 < 8; ++k4) {
                    float4 xv[8];
                    #pragma unroll
                    for (int ri = 0; ri < 8; ++ri)
                        xv[ri] = *(const float4*)(IN + (tr * 8 + ri) * HH + kb * 32 + k4 * 4);
                    #pragma unroll
                    for (int kk = 0; kk < 4; ++kk) {
                        const float* wrow = wt + (k4 * 4 + kk) * HH + tc * 8;
                        ulonglong2 w0 = *(const ulonglong2*)wrow;
                        ulonglong2 w1 = *(const ulonglong2*)(wrow + 4);
                        #pragma unroll
                        for (int ri = 0; ri < 8; ++ri) {
                            float xs = (kk == 0) ? xv[ri].x : (kk == 1) ? xv[ri].y
                                     : (kk == 2) ? xv[ri].z : xv[ri].w;
                            unsigned long long xp = pack2s(xs);
                            fma2(acc[ri][0], xp, w0.x);
                            fma2(acc[ri][1], xp, w0.y);
                            fma2(acc[ri][2], xp, w1.x);
                            fma2(acc[ri][3], xp, w1.y);
                        }
                    }
                }
                __syncthreads();
            }

            #pragma unroll
            for (int ri = 0; ri < 8; ++ri) {
                float2 a0 = unpack2(acc[ri][0]);
                float2 a1 = unpack2(acc[ri][1]);
                float2 a2 = unpack2(acc[ri][2]);
                float2 a3 = unpack2(acc[ri][3]);
                float* orow = OUT + (tr * 8 + ri) * HH + tc * 8;
                orow[0] = silu(a0.x); orow[1] = silu(a0.y);
                orow[2] = silu(a1.x); orow[3] = silu(a1.y);
                orow[4] = silu(a2.x); orow[5] = silu(a2.y);
                orow[6] = silu(a3.x); orow[7] = silu(a3.y);
            }
            __syncthreads();
            float* tmp = IN; IN = OUT; OUT = tmp;
        }
        // IN now holds final activations. Pool: thread owns column tid.
        {
            const int c = tid;
            #pragma unroll 4
            for (int r = 0; r < BM; ++r) {
                int g = rowg[r];
                if (g >= 0) accs[(g << 8) + c] += IN[(r << 8) + c];
            }
        }
        __syncthreads();
    }

    // flush block accumulator to global
    float* dst = g_pooled + head * (GG * 2 * HH) + branch * HH;
    for (int i = tid; i < GG * HH; i += 256) {
        float v = accs[i];
        if (v != 0.0f) atomicAdd(&dst[(i >> 8) * (2 * HH) + (i & 255)], v);
    }
}

// ---- MLP2 per (head, graph) + signed combine into out ----
__global__ void __launch_bounds__(256)
mlp2_kernel(const float* __restrict__ V1, const float* __restrict__ c1,
            const float* __restrict__ V2, const float* __restrict__ c2,
            const float* __restrict__ V3, const float* __restrict__ c3,
            float* __restrict__ out, int T) {
    __shared__ float x[512];
    __shared__ float h[256];
    __shared__ float red[8];
    const int head = blockIdx.x >> 6;
    const int g    = blockIdx.x & 63;
    const int tid  = threadIdx.x;

    const float* src = g_pooled + head * (GG * 2 * HH) + g * (2 * HH);
    x[tid]       = src[tid];
    x[tid + 256] = src[tid + 256];
    __syncthreads();

    float a = c1[tid];
    #pragma unroll 4
    for (int k = 0; k < 512; ++k) a = fmaf(x[k], __ldg(&V1[k * 256 + tid]), a);
    a = silu(a);
    __syncthreads();
    h[tid] = a;
    __syncthreads();

    float b = c2[tid];
    #pragma unroll 4
    for (int k = 0; k < 256; ++k) b = fmaf(h[k], __ldg(&V2[k * 256 + tid]), b);
    b = silu(b);
    __syncthreads();
    x[tid] = b;
    __syncthreads();

    const float sign = (head == 0) ? 1.0f : -1.0f;
    for (int t = 0; t < T; ++t) {
        float p = x[tid] * __ldg(&V3[tid * T + t]);
        #pragma unroll
        for (int o = 16; o; o >>= 1) p += __shfl_down_sync(0xFFFFFFFFu, p, o);
        if ((tid & 31) == 0) red[tid >> 5] = p;
        __syncthreads();
        if (tid == 0) {
            float s = c3[t];
            #pragma unroll
            for (int w = 0; w < 8; ++w) s += red[w];
            atomicAdd(&out[g * T + t], sign * s);
        }
        __syncthreads();
    }
}

extern "C" void kernel_launch(void* const* d_in, const int* in_sizes, int n_in,
                              void* d_out, int out_size) {
    // num_graphs may sit at index 12 (signature order) or 24 (dict order)
    int wb = (in_sizes[12] == 1) ? 13 : 12;

    const float* nf0 = (const float*)d_in[0];
    const float* ef0 = (const float*)d_in[1];
    const int*   ei0 = (const int*)d_in[2];
    const int*   bt0 = (const int*)d_in[3];
    const float* nf1 = (const float*)d_in[4];
    const float* ef1 = (const float*)d_in[5];
    const int*   ei1 = (const int*)d_in[6];
    const int*   bt1 = (const int*)d_in[7];
    const float* nf2 = (const float*)d_in[8];
    const float* ef2 = (const float*)d_in[9];
    const int*   ei2 = (const int*)d_in[10];
    const int*   bt2 = (const int*)d_in[11];
    const float* W1 = (const float*)d_in[wb + 0];
    const float* b1 = (const float*)d_in[wb + 1];
    const float* W2 = (const float*)d_in[wb + 2];
    const float* b2 = (const float*)d_in[wb + 3];
    const float* W3 = (const float*)d_in[wb + 4];
    const float* b3 = (const float*)d_in[wb + 5];
    const float* V1 = (const float*)d_in[wb + 6];
    const float* c1 = (const float*)d_in[wb + 7];
    const float* V2 = (const float*)d_in[wb + 8];
    const float* c2 = (const float*)d_in[wb + 9];
    const float* V3 = (const float*)d_in[wb + 10];
    const float* c3 = (const float*)d_in[wb + 11];
    float* out = (float*)d_out;
    int T = in_sizes[wb + 10] / HH;
    if (T < 1) T = 1;

    static int smem_set = 0;
    if (!smem_set) {
        cudaFuncSetAttribute(fused_mlp1_pool,
                             cudaFuncAttributeMaxDynamicSharedMemorySize, SMEM_BYTES);
        smem_set = 1;
    }

    int ztotal = 3 * GG * 2 * HH + out_size;
    zero_kernel<<<(ztotal + 255) / 256, 256>>>(out, out_size);
    fused_mlp1_pool<<<GRID1, 256, SMEM_BYTES>>>(
        nf0, ef0, ei0, bt0, nf1, ef1, ei1, bt1, nf2, ef2, ei2, bt2,
        W1, b1, W2, b2, W3, b3);
    mlp2_kernel<<<3 * GG, 256>>>(V1, c1, V2, c2, V3, c3, out, T);
}

// round 4
// speedup vs baseline: 2.0170x; 2.0170x over previous
#include <cuda_runtime.h>
#include <cuda_bf16.h>
#include <cstdint>

#define NN 10000
#define EE 160000
#define HH 256
#define GG 64
#define BM 64
#define NODE_BLKS 6
#define EDGE_BLKS 92
#define HEAD_SPAN (NODE_BLKS + EDGE_BLKS)
#define GRID1 (3 * HEAD_SPAN)

// shared memory layout (in floats)
#define SM_BUFA 0            // 64*256 = 16384
#define SM_BUFB 16384        // 64*256 = 16384
#define SM_W    32768        // 32*264 =  8448
#define SM_ACC  41216        // 64*256 = 16384
#define SM_ROWG 57600        // 64 ints
#define SMEM_BYTES ((57600 + 64) * 4)   // 230,656 B

__device__ float g_pooled[3 * GG * 2 * HH];

__device__ __forceinline__ float silu(float x) {
    return __fdividef(x, 1.0f + __expf(-x));
}
__device__ __forceinline__ unsigned tf32r(float x) {
    unsigned r;
    asm("cvt.rna.tf32.f32 %0, %1;" : "=r"(r) : "f"(x));
    return r;
}
__device__ __forceinline__ int swz(int r, int c) {
    return (((c >> 2) ^ (r & 7)) << 2) | (c & 3);
}
__device__ __forceinline__ void mma_tf32(float* c, const unsigned* a,
                                         unsigned b0, unsigned b1) {
    asm volatile(
        "mma.sync.aligned.m16n8k8.row.col.f32.tf32.tf32.f32 "
        "{%0,%1,%2,%3}, {%4,%5,%6,%7}, {%8,%9}, {%0,%1,%2,%3};"
        : "+f"(c[0]), "+f"(c[1]), "+f"(c[2]), "+f"(c[3])
        : "r"(a[0]), "r"(a[1]), "r"(a[2]), "r"(a[3]), "r"(b0), "r"(b1));
}

__global__ void zero_kernel(float* out, int out_size) {
    int i = blockIdx.x * 256 + threadIdx.x;
    int np = 3 * GG * 2 * HH;
    if (i < np) g_pooled[i] = 0.0f;
    else if (i - np < out_size) out[i - np] = 0.0f;
}

__global__ void __launch_bounds__(256, 1)
fused_mlp1_pool(const float* __restrict__ nf0, const float* __restrict__ ef0,
                const int* __restrict__ ei0, const int* __restrict__ bt0,
                const float* __restrict__ nf1, const float* __restrict__ ef1,
                const int* __restrict__ ei1, const int* __restrict__ bt1,
                const float* __restrict__ nf2, const float* __restrict__ ef2,
                const int* __restrict__ ei2, const int* __restrict__ bt2,
                const float* __restrict__ W1, const float* __restrict__ b1,
                const float* __restrict__ W2, const float* __restrict__ b2,
                const float* __restrict__ W3, const float* __restrict__ b3) {
    extern __shared__ float sm[];
    float* bufA = sm + SM_BUFA;
    float* bufB = sm + SM_BUFB;
    unsigned* Wu = (unsigned*)(sm + SM_W);     // [32][264] tf32 bits
    float* accs = sm + SM_ACC;
    int* rowg = (int*)(sm + SM_ROWG);

    const int tid = threadIdx.x;
    const int lane = tid & 31;
    const int warp = tid >> 5;
    const int wm = warp >> 2;       // 0..1 : rows [wm*32, wm*32+32)
    const int wn = warp & 3;        // 0..3 : cols [wn*64, wn*64+64)
    const int gID = lane >> 2;      // 0..7
    const int tg = lane & 3;        // 0..3

    const int head = blockIdx.x / HEAD_SPAN;
    const int j = blockIdx.x % HEAD_SPAN;

    const float* nf = (head == 0) ? nf0 : (head == 1) ? nf1 : nf2;
    const float* ef = (head == 0) ? ef0 : (head == 1) ? ef1 : ef2;
    const int* ei = (head == 0) ? ei0 : (head == 1) ? ei1 : ei2;
    const int* bt = (head == 0) ? bt0 : (head == 1) ? bt1 : bt2;

    int branch, P, p, nrows;
    if (j < NODE_BLKS) { branch = 0; P = NODE_BLKS; p = j;             nrows = NN; }
    else               { branch = 1; P = EDGE_BLKS; p = j - NODE_BLKS; nrows = EE; }
    const float* feats = branch ? ef : nf;
    const int ntiles = (nrows + BM - 1) >> 6;

    for (int i = tid; i < GG * HH; i += 256) accs[i] = 0.0f;

    const float* Ws[3] = {W1, W2, W3};
    const float* Bs[3] = {b1, b2, b3};

    for (int t = p; t < ntiles; t += P) {
        const int row0 = t << 6;
        const int rem = nrows - row0;

        if (tid < BM) {
            int r = row0 + tid;
            int g = -1;
            if (r < nrows) g = branch ? bt[ei[EE + r]] : bt[r];
            rowg[tid] = g;
        }
        // load input tile, round to tf32, store swizzled
        {
            const float4* f4 = (const float4*)feats + (size_t)row0 * (HH / 4);
            #pragma unroll
            for (int i = 0; i < 16; ++i) {
                int idx = tid + i * 256;          // 0..4095 float4s
                int r = idx >> 6;
                int cq = idx & 63;
                uint4 v = make_uint4(0u, 0u, 0u, 0u);
                if (r < rem) {
                    float4 f = f4[idx];
                    v.x = tf32r(f.x); v.y = tf32r(f.y);
                    v.z = tf32r(f.z); v.w = tf32r(f.w);
                }
                ((uint4*)bufA)[r * 64 + (cq ^ (r & 7))] = v;
            }
        }
        __syncthreads();

        unsigned* IN = (unsigned*)bufA;
        unsigned* OUT = (unsigned*)bufB;

        #pragma unroll
        for (int l = 0; l < 3; ++l) {
            const float* W = Ws[l];
            const float* Bv = Bs[l];

            float c[2][8][4];
            #pragma unroll
            for (int t8 = 0; t8 < 8; ++t8) {
                int n0 = wn * 64 + t8 * 8 + tg * 2;
                float bb0 = __ldg(&Bv[n0]);
                float bb1 = __ldg(&Bv[n0 + 1]);
                #pragma unroll
                for (int s = 0; s < 2; ++s) {
                    c[s][t8][0] = bb0; c[s][t8][1] = bb1;
                    c[s][t8][2] = bb0; c[s][t8][3] = bb1;
                }
            }

            for (int kb = 0; kb < 8; ++kb) {
                // stage 32x256 W chunk (rounded to tf32), stride 264
                {
                    const float4* wsrc = (const float4*)(W + kb * 32 * HH);
                    #pragma unroll
                    for (int i = 0; i < 8; ++i) {
                        int idx = tid + i * 256;      // 0..2047
                        int krel = idx >> 6;
                        int cq = idx & 63;
                        float4 f = wsrc[idx];
                        uint4 v;
                        v.x = tf32r(f.x); v.y = tf32r(f.y);
                        v.z = tf32r(f.z); v.w = tf32r(f.w);
                        ((uint4*)Wu)[krel * 66 + cq] = v;
                    }
                }
                __syncthreads();

                #pragma unroll
                for (int k8 = 0; k8 < 4; ++k8) {
                    const int kk0 = kb * 32 + k8 * 8;
                    // A fragments
                    unsigned a[2][4];
                    #pragma unroll
                    for (int s = 0; s < 2; ++s) {
                        int r = wm * 32 + s * 16 + gID;
                        int rx = r & 7;
                        int qa = ((kk0 >> 2) ^ rx) << 2;
                        int qb = (((kk0 >> 2) + 1) ^ rx) << 2;
                        int base = r * 256;
                        a[s][0] = IN[base + qa + tg];
                        a[s][1] = IN[base + 2048 + qa + tg];
                        a[s][2] = IN[base + qb + tg];
                        a[s][3] = IN[base + 2048 + qb + tg];
                    }
                    // B fragments + MMAs
                    const int krel = k8 * 8 + tg;
                    #pragma unroll
                    for (int t8 = 0; t8 < 8; ++t8) {
                        int n = wn * 64 + t8 * 8 + gID;
                        unsigned b0 = Wu[krel * 264 + n];
                        unsigned b1 = Wu[(krel + 4) * 264 + n];
                        mma_tf32(c[0][t8], a[0], b0, b1);
                        mma_tf32(c[1][t8], a[1], b0, b1);
                    }
                }
                __syncthreads();
            }

            // epilogue: silu (+ tf32 round for layers 0,1), swizzled store
            #pragma unroll
            for (int s = 0; s < 2; ++s) {
                int r = wm * 32 + s * 16 + gID;
                #pragma unroll
                for (int t8 = 0; t8 < 8; ++t8) {
                    int n0 = wn * 64 + t8 * 8 + tg * 2;
                    float v0 = silu(c[s][t8][0]);
                    float v1 = silu(c[s][t8][1]);
                    float v2 = silu(c[s][t8][2]);
                    float v3 = silu(c[s][t8][3]);
                    int o = r * 256 + swz(r, n0);
                    if (l < 2) {
                        OUT[o] = tf32r(v0);     OUT[o + 1] = tf32r(v1);
                        OUT[o + 2048] = tf32r(v2); OUT[o + 2049] = tf32r(v3);
                    } else {
                        OUT[o] = __float_as_uint(v0);
                        OUT[o + 1] = __float_as_uint(v1);
                        OUT[o + 2048] = __float_as_uint(v2);
                        OUT[o + 2049] = __float_as_uint(v3);
                    }
                }
            }
            __syncthreads();
            unsigned* tmp = IN; IN = OUT; OUT = tmp;
        }

        // pooling: thread owns column tid, swizzled reads
        {
            const float* fin = (const float*)IN;
            const int c = tid;
            #pragma unroll 4
            for (int r = 0; r < BM; ++r) {
                int g = rowg[r];
                if (g >= 0) accs[(g << 8) + c] += fin[(r << 8) + swz(r, c)];
            }
        }
        __syncthreads();
    }

    float* dst = g_pooled + head * (GG * 2 * HH) + branch * HH;
    for (int i = tid; i < GG * HH; i += 256) {
        float v = accs[i];
        if (v != 0.0f) atomicAdd(&dst[(i >> 8) * (2 * HH) + (i & 255)], v);
    }
}

__global__ void __launch_bounds__(256)
mlp2_kernel(const float* __restrict__ V1, const float* __restrict__ c1,
            const float* __restrict__ V2, const float* __restrict__ c2,
            const float* __restrict__ V3, const float* __restrict__ c3,
            float* __restrict__ out, int T) {
    __shared__ float x[512];
    __shared__ float h[256];
    __shared__ float red[8];
    const int head = blockIdx.x >> 6;
    const int g = blockIdx.x & 63;
    const int tid = threadIdx.x;

    const float* src = g_pooled + head * (GG * 2 * HH) + g * (2 * HH);
    x[tid] = src[tid];
    x[tid + 256] = src[tid + 256];
    __syncthreads();

    float a = c1[tid];
    #pragma unroll 4
    for (int k = 0; k < 512; ++k) a = fmaf(x[k], __ldg(&V1[k * 256 + tid]), a);
    a = silu(a);
    __syncthreads();
    h[tid] = a;
    __syncthreads();

    float b = c2[tid];
    #pragma unroll 4
    for (int k = 0; k < 256; ++k) b = fmaf(h[k], __ldg(&V2[k * 256 + tid]), b);
    b = silu(b);
    __syncthreads();
    x[tid] = b;
    __syncthreads();

    const float sign = (head == 0) ? 1.0f : -1.0f;
    for (int t = 0; t < T; ++t) {
        float p = x[tid] * __ldg(&V3[tid * T + t]);
        #pragma unroll
        for (int o = 16; o; o >>= 1) p += __shfl_down_sync(0xFFFFFFFFu, p, o);
        if ((tid & 31) == 0) red[tid >> 5] = p;
        __syncthreads();
        if (tid == 0) {
            float s = c3[t];
            #pragma unroll
            for (int w = 0; w < 8; ++w) s += red[w];
            atomicAdd(&out[g * T + t], sign * s);
        }
        __syncthreads();
    }
}

extern "C" void kernel_launch(void* const* d_in, const int* in_sizes, int n_in,
                              void* d_out, int out_size) {
    int wb = (in_sizes[12] == 1) ? 13 : 12;

    const float* nf0 = (const float*)d_in[0];
    const float* ef0 = (const float*)d_in[1];
    const int*   ei0 = (const int*)d_in[2];
    const int*   bt0 = (const int*)d_in[3];
    const float* nf1 = (const float*)d_in[4];
    const float* ef1 = (const float*)d_in[5];
    const int*   ei1 = (const int*)d_in[6];
    const int*   bt1 = (const int*)d_in[7];
    const float* nf2 = (const float*)d_in[8];
    const float* ef2 = (const float*)d_in[9];
    const int*   ei2 = (const int*)d_in[10];
    const int*   bt2 = (const int*)d_in[11];
    const float* W1 = (const float*)d_in[wb + 0];
    const float* b1 = (const float*)d_in[wb + 1];
    const float* W2 = (const float*)d_in[wb + 2];
    const float* b2 = (const float*)d_in[wb + 3];
    const float* W3 = (const float*)d_in[wb + 4];
    const float* b3 = (const float*)d_in[wb + 5];
    const float* V1 = (const float*)d_in[wb + 6];
    const float* c1 = (const float*)d_in[wb + 7];
    const float* V2 = (const float*)d_in[wb + 8];
    const float* c2 = (const float*)d_in[wb + 9];
    const float* V3 = (const float*)d_in[wb + 10];
    const float* c3 = (const float*)d_in[wb + 11];
    float* out = (float*)d_out;
    int T = in_sizes[wb + 10] / HH;
    if (T < 1) T = 1;

    static int smem_set = 0;
    if (!smem_set) {
        cudaFuncSetAttribute(fused_mlp1_pool,
                             cudaFuncAttributeMaxDynamicSharedMemorySize, SMEM_BYTES);
        smem_set = 1;
    }

    int ztotal = 3 * GG * 2 * HH + out_size;
    zero_kernel<<<(ztotal + 255) / 256, 256>>>(out, out_size);
    fused_mlp1_pool<<<GRID1, 256, SMEM_BYTES>>>(
        nf0, ef0, ei0, bt0, nf1, ef1, ei1, bt1, nf2, ef2, ei2, bt2,
        W1, b1, W2, b2, W3, b3);
    mlp2_kernel<<<3 * GG, 256>>>(V1, c1, V2, c2, V3, c3, out, T);
}